// round 15
// baseline (speedup 1.0000x reference)
#include <cuda_runtime.h>
#include <cuda_bf16.h>
#include <cstddef>

#define N_NODES 50000
#define N_EDGES 800000
#define IN_F    128
#define OUT_F   64
#define ALPHA   0.2f
#define INV_SQRT_F 0.125f   /* 1/sqrt(64) */

// Scratch (no device mallocs allowed)
__device__ float g_data[(size_t)N_NODES * OUT_F];   // h @ W^T + b
__device__ float g_ssrc[N_NODES];                   // data . a_src
__device__ float g_sdst[N_NODES];                   // data . a_dst
__device__ float g_rowsum[N_NODES];
__device__ int   g_stride;                          // 1 = int32 adj, 2 = int64 adj

// ---------------------------------------------------------------------------
// Kernel 0: zero output accumulator + rowsum, detect adj element width.
// If adj is really int64 (little-endian, values < 2^31), every odd int32 word
// of the buffer is zero. Genuine int32 data has ~0 chance of 4 zeros in a row.
// ---------------------------------------------------------------------------
__global__ void init_kernel(float* __restrict__ out, const int* __restrict__ adj32) {
    int i = blockIdx.x * blockDim.x + threadIdx.x;
    if (i < N_NODES * OUT_F) out[i] = 0.0f;
    if (i < N_NODES) g_rowsum[i] = 0.0f;
    if (i == 0) {
        bool is64 = (adj32[1] == 0) && (adj32[3] == 0) &&
                    (adj32[5] == 0) && (adj32[7] == 0);
        g_stride = is64 ? 2 : 1;
    }
}

// ---------------------------------------------------------------------------
// Kernel 1: data = h @ W^T + b ; s_src = data.a_src ; s_dst = data.a_dst
// 256 threads = 4 groups of 64; each group computes one node's 64 outputs.
// ---------------------------------------------------------------------------
#define NODES_PER_BLOCK 16

__global__ void __launch_bounds__(256) gemm_score_kernel(
    const float* __restrict__ h,
    const float* __restrict__ W,      // [OUT_F][IN_F] row-major
    const float* __restrict__ b,      // [OUT_F]
    const float* __restrict__ a)      // [2*OUT_F]
{
    __shared__ float sW[IN_F][OUT_F];   // transposed: sW[k][o], 32 KB
    __shared__ float sA[2 * OUT_F];
    __shared__ float sB[OUT_F];
    __shared__ float sH[4][IN_F];
    __shared__ float sPart[4][2][2];    // [group][warpInGroup][src/dst]

    int t = threadIdx.x;
    for (int i = t; i < IN_F * OUT_F; i += 256) {
        int o = i / IN_F, k = i % IN_F;
        sW[k][o] = W[i];
    }
    if (t < 2 * OUT_F) sA[t] = a[t];
    if (t < OUT_F)     sB[t] = b[t];

    int ox        = t & 63;         // output feature
    int grp       = t >> 6;         // 0..3
    int lane      = t & 31;
    int warpInGrp = (t >> 5) & 1;

    int node_base = blockIdx.x * NODES_PER_BLOCK;

    for (int it = 0; it < NODES_PER_BLOCK / 4; ++it) {
        int node = node_base + it * 4 + grp;
        __syncthreads();   // protect sH/sPart reuse across iterations
        if (node < N_NODES) {
            sH[grp][ox]      = h[(size_t)node * IN_F + ox];
            sH[grp][ox + 64] = h[(size_t)node * IN_F + ox + 64];
        }
        __syncthreads();
        if (node < N_NODES) {
            float acc = 0.0f;
            #pragma unroll
            for (int k = 0; k < IN_F; ++k)
                acc = fmaf(sH[grp][k], sW[k][ox], acc);
            float v = acc + sB[ox];
            g_data[(size_t)node * OUT_F + ox] = v;

            float ps = v * sA[ox];
            float pd = v * sA[OUT_F + ox];
            #pragma unroll
            for (int off = 16; off; off >>= 1) {
                ps += __shfl_xor_sync(0xffffffffu, ps, off);
                pd += __shfl_xor_sync(0xffffffffu, pd, off);
            }
            if (lane == 0) {
                sPart[grp][warpInGrp][0] = ps;
                sPart[grp][warpInGrp][1] = pd;
            }
        }
        __syncthreads();
        if (node < N_NODES && ox == 0) {
            g_ssrc[node] = sPart[grp][0][0] + sPart[grp][1][0];
            g_sdst[node] = sPart[grp][0][1] + sPart[grp][1][1];
        }
    }
}

// ---------------------------------------------------------------------------
// Kernel 2: edge scatter. 16 threads per edge (2 edges per warp), grid-stride.
//   e  = exp(leaky_relu(s_src[src] + s_dst[dst]) * 0.125)
//   rowsum[src] += e ;  out[src][:] += e * data[dst][:]
// Each of the 16 lanes covers 4 floats with one red.global.add.v4.f32.
// ---------------------------------------------------------------------------
__global__ void __launch_bounds__(256) edge_kernel(
    const int* __restrict__ adj32,
    float* __restrict__ out)
{
    int gtid   = blockIdx.x * blockDim.x + threadIdx.x;
    int eg     = gtid >> 4;                       // edge-group id
    int hl     = threadIdx.x & 15;                // lane within the 16-group
    int negs   = (gridDim.x * blockDim.x) >> 4;
    int stride = g_stride;                        // 1 (int32) or 2 (int64)

    for (int e = eg; e < N_EDGES; e += negs) {
        int src = __ldg(adj32 + (size_t)e * stride);
        int dst = __ldg(adj32 + ((size_t)N_EDGES + e) * stride);

        float s  = g_ssrc[src] + g_sdst[dst];
        float lr = s > 0.0f ? s : ALPHA * s;
        float ee = __expf(lr * INV_SQRT_F);

        float4 d4 = *reinterpret_cast<const float4*>(
                        g_data + (size_t)dst * OUT_F + 4 * hl);
        float* oo = out + (size_t)src * OUT_F + 4 * hl;

        asm volatile("red.global.add.v4.f32 [%0], {%1, %2, %3, %4};"
                     :: "l"(oo),
                        "f"(ee * d4.x), "f"(ee * d4.y),
                        "f"(ee * d4.z), "f"(ee * d4.w)
                     : "memory");

        if (hl == 0) atomicAdd(g_rowsum + src, ee);
    }
}

// ---------------------------------------------------------------------------
// Kernel 3: finalize — divide by rowsum; rowsum==0 rows get data row verbatim
// ---------------------------------------------------------------------------
__global__ void finalize_kernel(float* __restrict__ out) {
    int i = blockIdx.x * blockDim.x + threadIdx.x;
    if (i >= N_NODES * OUT_F) return;
    int node = i >> 6;
    float rs = g_rowsum[node];
    if (rs == 0.0f) {
        out[i] = g_data[i];         // (h_prime=0) + data, divided by 1
    } else {
        out[i] = out[i] / rs;
    }
}

// ---------------------------------------------------------------------------
extern "C" void kernel_launch(void* const* d_in, const int* in_sizes, int n_in,
                              void* d_out, int out_size) {
    const float* h     = (const float*)d_in[0];
    const int*   adj32 = (const int*)d_in[1];
    const float* W_w   = (const float*)d_in[2];
    const float* W_b   = (const float*)d_in[3];
    const float* a     = (const float*)d_in[4];
    float*       out   = (float*)d_out;

    (void)in_sizes; (void)n_in; (void)out_size;

    const int TOT = N_NODES * OUT_F;

    init_kernel<<<(TOT + 255) / 256, 256>>>(out, adj32);

    gemm_score_kernel<<<(N_NODES + NODES_PER_BLOCK - 1) / NODES_PER_BLOCK, 256>>>(
        h, W_w, W_b, a);

    // 2368 blocks * 16 edge-groups = 37888 groups, ~21 edges each
    edge_kernel<<<2368, 256>>>(adj32, out);

    finalize_kernel<<<(TOT + 255) / 256, 256>>>(out);
}

// round 16
// speedup vs baseline: 1.0392x; 1.0392x over previous
#include <cuda_runtime.h>
#include <cuda_bf16.h>
#include <cstddef>

#define N_NODES 50000
#define N_EDGES 800000
#define IN_F    128
#define OUT_F   64
#define ALPHA   0.2f
#define INV_SQRT_F 0.125f   /* 1/sqrt(64) */

#define SCAN_BLOCK 512
#define N_SCAN_BLOCKS ((N_NODES + SCAN_BLOCK - 1) / SCAN_BLOCK)   // 98

// ---- device scratch (no mallocs allowed) ----------------------------------
__device__ float g_data[(size_t)N_NODES * OUT_F];   // h @ W^T + b
__device__ float g_ssrc[N_NODES];                   // data . a_src
__device__ float g_sdst[N_NODES];                   // data . a_dst
__device__ int   g_count[N_NODES];                  // out-degree per src
__device__ int   g_start[N_NODES];                  // CSR row start (excl scan)
__device__ int   g_cursor[N_NODES];                 // scatter write cursor
__device__ int   g_bsum[N_SCAN_BLOCKS];
__device__ int   g_boff[N_SCAN_BLOCKS];
__device__ int2  g_edges[N_EDGES];                  // packed {dst, ee-bits}
__device__ int   g_stride;                          // 1 = int32 adj, 2 = int64 adj

// ---------------------------------------------------------------------------
// K0: zero histogram + detect adj element width (int64 => odd words are 0)
// ---------------------------------------------------------------------------
__global__ void zero_kernel(const int* __restrict__ adj32) {
    int i = blockIdx.x * blockDim.x + threadIdx.x;
    if (i < N_NODES) g_count[i] = 0;
    if (i == 0) {
        bool is64 = (adj32[1] == 0) && (adj32[3] == 0) &&
                    (adj32[5] == 0) && (adj32[7] == 0);
        g_stride = is64 ? 2 : 1;
    }
}

// ---------------------------------------------------------------------------
// K1: histogram of src
// ---------------------------------------------------------------------------
__global__ void __launch_bounds__(256) hist_kernel(const int* __restrict__ adj32) {
    int e = blockIdx.x * blockDim.x + threadIdx.x;
    if (e < N_EDGES) {
        int src = __ldg(adj32 + (size_t)e * g_stride);
        atomicAdd(&g_count[src], 1);
    }
}

// ---------------------------------------------------------------------------
// K2a: per-block exclusive scan of g_count (512 nodes per block)
// ---------------------------------------------------------------------------
__global__ void __launch_bounds__(SCAN_BLOCK) scan1_kernel() {
    __shared__ int wsum[SCAN_BLOCK / 32];
    int node = blockIdx.x * SCAN_BLOCK + threadIdx.x;
    int lane = threadIdx.x & 31;
    int wid  = threadIdx.x >> 5;

    int v = (node < N_NODES) ? g_count[node] : 0;
    int inc = v;
    #pragma unroll
    for (int off = 1; off < 32; off <<= 1) {
        int n = __shfl_up_sync(0xffffffffu, inc, off);
        if (lane >= off) inc += n;
    }
    if (lane == 31) wsum[wid] = inc;
    __syncthreads();
    if (threadIdx.x < SCAN_BLOCK / 32) {          // 16 threads
        int s = wsum[threadIdx.x];
        int si = s;
        #pragma unroll
        for (int off = 1; off < 16; off <<= 1) {
            int n = __shfl_up_sync(0xffffu, si, off);
            if (threadIdx.x >= off) si += n;
        }
        wsum[threadIdx.x] = si - s;               // exclusive warp offset
        if (threadIdx.x == SCAN_BLOCK / 32 - 1) g_bsum[blockIdx.x] = si;
    }
    __syncthreads();
    if (node < N_NODES) g_start[node] = wsum[wid] + inc - v;   // block-local excl
}

// ---------------------------------------------------------------------------
// K2b: single-block exclusive scan of the 98 block sums
// ---------------------------------------------------------------------------
__global__ void scan2_kernel() {
    __shared__ int wsum[4];
    int i    = threadIdx.x;                       // 128 threads
    int lane = i & 31;
    int wid  = i >> 5;
    int v = (i < N_SCAN_BLOCKS) ? g_bsum[i] : 0;
    int inc = v;
    #pragma unroll
    for (int off = 1; off < 32; off <<= 1) {
        int n = __shfl_up_sync(0xffffffffu, inc, off);
        if (lane >= off) inc += n;
    }
    if (lane == 31) wsum[wid] = inc;
    __syncthreads();
    if (i < 4) {
        int s = wsum[i];
        int si = s;
        #pragma unroll
        for (int off = 1; off < 4; off <<= 1) {
            int n = __shfl_up_sync(0xfu, si, off);
            if (i >= off) si += n;
        }
        wsum[i] = si - s;
    }
    __syncthreads();
    if (i < N_SCAN_BLOCKS) g_boff[i] = wsum[wid] + inc - v;
}

// ---------------------------------------------------------------------------
// K2c: add block offsets, seed cursors
// ---------------------------------------------------------------------------
__global__ void scan3_kernel() {
    int i = blockIdx.x * blockDim.x + threadIdx.x;
    if (i < N_NODES) {
        int s = g_start[i] + g_boff[i / SCAN_BLOCK];
        g_start[i]  = s;
        g_cursor[i] = s;
    }
}

// ---------------------------------------------------------------------------
// K3: data = h @ W^T + b ; s_src = data.a_src ; s_dst = data.a_dst
// ---------------------------------------------------------------------------
#define NODES_PER_BLOCK 16

__global__ void __launch_bounds__(256) gemm_score_kernel(
    const float* __restrict__ h,
    const float* __restrict__ W,      // [OUT_F][IN_F] row-major
    const float* __restrict__ b,      // [OUT_F]
    const float* __restrict__ a)      // [2*OUT_F]
{
    __shared__ float sW[IN_F][OUT_F];   // transposed: sW[k][o]
    __shared__ float sA[2 * OUT_F];
    __shared__ float sB[OUT_F];
    __shared__ float sH[4][IN_F];
    __shared__ float sPart[4][2][2];

    int t = threadIdx.x;
    for (int i = t; i < IN_F * OUT_F; i += 256) {
        int o = i / IN_F, k = i % IN_F;
        sW[k][o] = W[i];
    }
    if (t < 2 * OUT_F) sA[t] = a[t];
    if (t < OUT_F)     sB[t] = b[t];

    int ox        = t & 63;
    int grp       = t >> 6;
    int lane      = t & 31;
    int warpInGrp = (t >> 5) & 1;

    int node_base = blockIdx.x * NODES_PER_BLOCK;

    for (int it = 0; it < NODES_PER_BLOCK / 4; ++it) {
        int node = node_base + it * 4 + grp;
        __syncthreads();
        if (node < N_NODES) {
            sH[grp][ox]      = h[(size_t)node * IN_F + ox];
            sH[grp][ox + 64] = h[(size_t)node * IN_F + ox + 64];
        }
        __syncthreads();
        if (node < N_NODES) {
            float acc = 0.0f;
            #pragma unroll
            for (int k = 0; k < IN_F; ++k)
                acc = fmaf(sH[grp][k], sW[k][ox], acc);
            float v = acc + sB[ox];
            g_data[(size_t)node * OUT_F + ox] = v;

            float ps = v * sA[ox];
            float pd = v * sA[OUT_F + ox];
            #pragma unroll
            for (int off = 16; off; off >>= 1) {
                ps += __shfl_xor_sync(0xffffffffu, ps, off);
                pd += __shfl_xor_sync(0xffffffffu, pd, off);
            }
            if (lane == 0) {
                sPart[grp][warpInGrp][0] = ps;
                sPart[grp][warpInGrp][1] = pd;
            }
        }
        __syncthreads();
        if (node < N_NODES && ox == 0) {
            g_ssrc[node] = sPart[grp][0][0] + sPart[grp][1][0];
            g_sdst[node] = sPart[grp][0][1] + sPart[grp][1][1];
        }
    }
}

// ---------------------------------------------------------------------------
// K4: scatter edges into CSR order with precomputed exp weight
// ---------------------------------------------------------------------------
__global__ void __launch_bounds__(256) scatter_kernel(const int* __restrict__ adj32) {
    int e = blockIdx.x * blockDim.x + threadIdx.x;
    if (e >= N_EDGES) return;
    int stride = g_stride;
    int src = __ldg(adj32 + (size_t)e * stride);
    int dst = __ldg(adj32 + ((size_t)N_EDGES + e) * stride);

    float s  = g_ssrc[src] + g_sdst[dst];
    float lr = s > 0.0f ? s : ALPHA * s;
    float ee = __expf(lr * INV_SQRT_F);

    int pos = atomicAdd(&g_cursor[src], 1);
    g_edges[pos] = make_int2(dst, __float_as_int(ee));
}

// ---------------------------------------------------------------------------
// K5: gather — one warp per node, register accumulation, fused finalize
// ---------------------------------------------------------------------------
__global__ void __launch_bounds__(256) gather_kernel(float* __restrict__ out) {
    int warp = (blockIdx.x * blockDim.x + threadIdx.x) >> 5;
    int lane = threadIdx.x & 31;
    if (warp >= N_NODES) return;

    int start = g_start[warp];
    int cnt   = g_count[warp];

    float a0 = 0.0f, a1 = 0.0f, rs = 0.0f;
    const int2* ep = g_edges + start;

    #pragma unroll 2
    for (int j = 0; j < cnt; ++j) {
        int2 ed = __ldg(ep + j);
        float ee = __int_as_float(ed.y);
        const float* dd = g_data + (size_t)ed.x * OUT_F;
        a0 = fmaf(ee, __ldg(dd + lane),      a0);
        a1 = fmaf(ee, __ldg(dd + lane + 32), a1);
        rs += ee;
    }

    size_t o = (size_t)warp * OUT_F;
    if (rs == 0.0f) {           // no edges (or all weights underflowed): out = data
        out[o + lane]      = g_data[o + lane];
        out[o + lane + 32] = g_data[o + lane + 32];
    } else {
        out[o + lane]      = a0 / rs;
        out[o + lane + 32] = a1 / rs;
    }
}

// ---------------------------------------------------------------------------
extern "C" void kernel_launch(void* const* d_in, const int* in_sizes, int n_in,
                              void* d_out, int out_size) {
    const float* h     = (const float*)d_in[0];
    const int*   adj32 = (const int*)d_in[1];
    const float* W_w   = (const float*)d_in[2];
    const float* W_b   = (const float*)d_in[3];
    const float* a     = (const float*)d_in[4];
    float*       out   = (float*)d_out;

    (void)in_sizes; (void)n_in; (void)out_size;

    zero_kernel<<<(N_NODES + 255) / 256, 256>>>(adj32);
    hist_kernel<<<(N_EDGES + 255) / 256, 256>>>(adj32);
    scan1_kernel<<<N_SCAN_BLOCKS, SCAN_BLOCK>>>();
    scan2_kernel<<<1, 128>>>();
    scan3_kernel<<<(N_NODES + 255) / 256, 256>>>();

    gemm_score_kernel<<<(N_NODES + NODES_PER_BLOCK - 1) / NODES_PER_BLOCK, 256>>>(
        h, W_w, W_b, a);

    scatter_kernel<<<(N_EDGES + 255) / 256, 256>>>(adj32);

    // 50000 warps, 8 per block
    gather_kernel<<<(N_NODES * 32 + 255) / 256, 256>>>(out);
}

// round 17
// speedup vs baseline: 1.0421x; 1.0028x over previous
#include <cuda_runtime.h>
#include <cuda_bf16.h>
#include <cstddef>

#define N_NODES 50000
#define N_EDGES 800000
#define IN_F    128
#define OUT_F   64
#define ALPHA   0.2f
#define INV_SQRT_F 0.125f   /* 1/sqrt(64) */

#define SCAN_BLOCK 512
#define N_SCAN_BLOCKS ((N_NODES + SCAN_BLOCK - 1) / SCAN_BLOCK)   // 98

// ---- device scratch (no mallocs allowed) ----------------------------------
__device__ float g_data[(size_t)N_NODES * OUT_F];   // h @ W^T + b
__device__ float g_ssrc[N_NODES];                   // data . a_src
__device__ float g_sdst[N_NODES];                   // data . a_dst
__device__ int   g_count[N_NODES];                  // out-degree per src
__device__ int   g_start[N_NODES];                  // CSR row start (excl scan)
__device__ int   g_cursor[N_NODES];                 // scatter write cursor
__device__ int   g_bsum[N_SCAN_BLOCKS];
__device__ int   g_boff[N_SCAN_BLOCKS];
__device__ int2  g_edges[N_EDGES];                  // packed {dst, ee-bits}
__device__ int   g_stride;                          // 1 = int32 adj, 2 = int64 adj

// ---------------------------------------------------------------------------
// K0: zero histogram + detect adj element width (int64 => odd words are 0)
// ---------------------------------------------------------------------------
__global__ void zero_kernel(const int* __restrict__ adj32) {
    int i = blockIdx.x * blockDim.x + threadIdx.x;
    if (i < N_NODES) g_count[i] = 0;
    if (i == 0) {
        bool is64 = (adj32[1] == 0) && (adj32[3] == 0) &&
                    (adj32[5] == 0) && (adj32[7] == 0);
        g_stride = is64 ? 2 : 1;
    }
}

// ---------------------------------------------------------------------------
// K1: histogram of src
// ---------------------------------------------------------------------------
__global__ void __launch_bounds__(256) hist_kernel(const int* __restrict__ adj32) {
    int e = blockIdx.x * blockDim.x + threadIdx.x;
    if (e < N_EDGES) {
        int src = __ldg(adj32 + (size_t)e * g_stride);
        atomicAdd(&g_count[src], 1);
    }
}

// ---------------------------------------------------------------------------
// K2a: per-block exclusive scan of g_count (512 nodes per block)
// ---------------------------------------------------------------------------
__global__ void __launch_bounds__(SCAN_BLOCK) scan1_kernel() {
    __shared__ int wsum[SCAN_BLOCK / 32];
    int node = blockIdx.x * SCAN_BLOCK + threadIdx.x;
    int lane = threadIdx.x & 31;
    int wid  = threadIdx.x >> 5;

    int v = (node < N_NODES) ? g_count[node] : 0;
    int inc = v;
    #pragma unroll
    for (int off = 1; off < 32; off <<= 1) {
        int n = __shfl_up_sync(0xffffffffu, inc, off);
        if (lane >= off) inc += n;
    }
    if (lane == 31) wsum[wid] = inc;
    __syncthreads();
    if (threadIdx.x < SCAN_BLOCK / 32) {          // 16 threads
        int s = wsum[threadIdx.x];
        int si = s;
        #pragma unroll
        for (int off = 1; off < 16; off <<= 1) {
            int n = __shfl_up_sync(0xffffu, si, off);
            if (threadIdx.x >= off) si += n;
        }
        wsum[threadIdx.x] = si - s;               // exclusive warp offset
        if (threadIdx.x == SCAN_BLOCK / 32 - 1) g_bsum[blockIdx.x] = si;
    }
    __syncthreads();
    if (node < N_NODES) g_start[node] = wsum[wid] + inc - v;   // block-local excl
}

// ---------------------------------------------------------------------------
// K2b: single-block exclusive scan of the 98 block sums
// ---------------------------------------------------------------------------
__global__ void scan2_kernel() {
    __shared__ int wsum[4];
    int i    = threadIdx.x;                       // 128 threads
    int lane = i & 31;
    int wid  = i >> 5;
    int v = (i < N_SCAN_BLOCKS) ? g_bsum[i] : 0;
    int inc = v;
    #pragma unroll
    for (int off = 1; off < 32; off <<= 1) {
        int n = __shfl_up_sync(0xffffffffu, inc, off);
        if (lane >= off) inc += n;
    }
    if (lane == 31) wsum[wid] = inc;
    __syncthreads();
    if (i < 4) {
        int s = wsum[i];
        int si = s;
        #pragma unroll
        for (int off = 1; off < 4; off <<= 1) {
            int n = __shfl_up_sync(0xfu, si, off);
            if (i >= off) si += n;
        }
        wsum[i] = si - s;
    }
    __syncthreads();
    if (i < N_SCAN_BLOCKS) g_boff[i] = wsum[wid] + inc - v;
}

// ---------------------------------------------------------------------------
// K2c: add block offsets, seed cursors
// ---------------------------------------------------------------------------
__global__ void scan3_kernel() {
    int i = blockIdx.x * blockDim.x + threadIdx.x;
    if (i < N_NODES) {
        int s = g_start[i] + g_boff[i / SCAN_BLOCK];
        g_start[i]  = s;
        g_cursor[i] = s;
    }
}

// ---------------------------------------------------------------------------
// K3: data = h @ W^T + b ; s_src = data.a_src ; s_dst = data.a_dst
// ---------------------------------------------------------------------------
#define NODES_PER_BLOCK 16

__global__ void __launch_bounds__(256) gemm_score_kernel(
    const float* __restrict__ h,
    const float* __restrict__ W,      // [OUT_F][IN_F] row-major
    const float* __restrict__ b,      // [OUT_F]
    const float* __restrict__ a)      // [2*OUT_F]
{
    __shared__ float sW[IN_F][OUT_F];   // transposed: sW[k][o]
    __shared__ float sA[2 * OUT_F];
    __shared__ float sB[OUT_F];
    __shared__ float sH[4][IN_F];
    __shared__ float sPart[4][2][2];

    int t = threadIdx.x;
    for (int i = t; i < IN_F * OUT_F; i += 256) {
        int o = i / IN_F, k = i % IN_F;
        sW[k][o] = W[i];
    }
    if (t < 2 * OUT_F) sA[t] = a[t];
    if (t < OUT_F)     sB[t] = b[t];

    int ox        = t & 63;
    int grp       = t >> 6;
    int lane      = t & 31;
    int warpInGrp = (t >> 5) & 1;

    int node_base = blockIdx.x * NODES_PER_BLOCK;

    for (int it = 0; it < NODES_PER_BLOCK / 4; ++it) {
        int node = node_base + it * 4 + grp;
        __syncthreads();
        if (node < N_NODES) {
            sH[grp][ox]      = h[(size_t)node * IN_F + ox];
            sH[grp][ox + 64] = h[(size_t)node * IN_F + ox + 64];
        }
        __syncthreads();
        if (node < N_NODES) {
            float acc = 0.0f;
            #pragma unroll
            for (int k = 0; k < IN_F; ++k)
                acc = fmaf(sH[grp][k], sW[k][ox], acc);
            float v = acc + sB[ox];
            g_data[(size_t)node * OUT_F + ox] = v;

            float ps = v * sA[ox];
            float pd = v * sA[OUT_F + ox];
            #pragma unroll
            for (int off = 16; off; off >>= 1) {
                ps += __shfl_xor_sync(0xffffffffu, ps, off);
                pd += __shfl_xor_sync(0xffffffffu, pd, off);
            }
            if (lane == 0) {
                sPart[grp][warpInGrp][0] = ps;
                sPart[grp][warpInGrp][1] = pd;
            }
        }
        __syncthreads();
        if (node < N_NODES && ox == 0) {
            g_ssrc[node] = sPart[grp][0][0] + sPart[grp][1][0];
            g_sdst[node] = sPart[grp][0][1] + sPart[grp][1][1];
        }
    }
}

// ---------------------------------------------------------------------------
// K4: scatter edges into CSR order with precomputed exp weight
// ---------------------------------------------------------------------------
__global__ void __launch_bounds__(256) scatter_kernel(const int* __restrict__ adj32) {
    int e = blockIdx.x * blockDim.x + threadIdx.x;
    if (e >= N_EDGES) return;
    int stride = g_stride;
    int src = __ldg(adj32 + (size_t)e * stride);
    int dst = __ldg(adj32 + ((size_t)N_EDGES + e) * stride);

    float s  = g_ssrc[src] + g_sdst[dst];
    float lr = s > 0.0f ? s : ALPHA * s;
    float ee = __expf(lr * INV_SQRT_F);

    int pos = atomicAdd(&g_cursor[src], 1);
    g_edges[pos] = make_int2(dst, __float_as_int(ee));
}

// ---------------------------------------------------------------------------
// K5: gather — one warp per node, register accumulation, fused finalize
// ---------------------------------------------------------------------------
__global__ void __launch_bounds__(256) gather_kernel(float* __restrict__ out) {
    int warp = (blockIdx.x * blockDim.x + threadIdx.x) >> 5;
    int lane = threadIdx.x & 31;
    if (warp >= N_NODES) return;

    int start = g_start[warp];
    int cnt   = g_count[warp];

    float a0 = 0.0f, a1 = 0.0f, rs = 0.0f;
    const int2* ep = g_edges + start;

    #pragma unroll 2
    for (int j = 0; j < cnt; ++j) {
        int2 ed = __ldg(ep + j);
        float ee = __int_as_float(ed.y);
        const float* dd = g_data + (size_t)ed.x * OUT_F;
        a0 = fmaf(ee, __ldg(dd + lane),      a0);
        a1 = fmaf(ee, __ldg(dd + lane + 32), a1);
        rs += ee;
    }

    size_t o = (size_t)warp * OUT_F;
    if (rs == 0.0f) {           // no edges (or all weights underflowed): out = data
        out[o + lane]      = g_data[o + lane];
        out[o + lane + 32] = g_data[o + lane + 32];
    } else {
        out[o + lane]      = a0 / rs;
        out[o + lane + 32] = a1 / rs;
    }
}

// ---------------------------------------------------------------------------
extern "C" void kernel_launch(void* const* d_in, const int* in_sizes, int n_in,
                              void* d_out, int out_size) {
    const float* h     = (const float*)d_in[0];
    const int*   adj32 = (const int*)d_in[1];
    const float* W_w   = (const float*)d_in[2];
    const float* W_b   = (const float*)d_in[3];
    const float* a     = (const float*)d_in[4];
    float*       out   = (float*)d_out;

    (void)in_sizes; (void)n_in; (void)out_size;

    zero_kernel<<<(N_NODES + 255) / 256, 256>>>(adj32);
    hist_kernel<<<(N_EDGES + 255) / 256, 256>>>(adj32);
    scan1_kernel<<<N_SCAN_BLOCKS, SCAN_BLOCK>>>();
    scan2_kernel<<<1, 128>>>();
    scan3_kernel<<<(N_NODES + 255) / 256, 256>>>();

    gemm_score_kernel<<<(N_NODES + NODES_PER_BLOCK - 1) / NODES_PER_BLOCK, 256>>>(
        h, W_w, W_b, a);

    scatter_kernel<<<(N_EDGES + 255) / 256, 256>>>(adj32);

    // 50000 warps, 8 per block
    gather_kernel<<<(N_NODES * 32 + 255) / 256, 256>>>(out);
}